// round 16
// baseline (speedup 1.0000x reference)
#include <cuda_runtime.h>
#include <cuda_bf16.h>
#include <cstdint>

constexpr int Bsz = 4, Np = 2304, Cc = 2304, Ee = 2304, E2 = 4608;
constexpr size_t PLANE = (size_t)Np * Cc;
constexpr int WT = 640;
constexpr size_t WPV = (size_t)WT * 2304;
constexpr size_t WPU = (size_t)2304 * 2304;

// ---------------- scratch ----------------
__device__ __nv_bfloat16 gV_h[(size_t)36*WPV], gV_l[(size_t)36*WPV];
__device__ __nv_bfloat16 gU_h[(size_t)36*WPU], gU_l[(size_t)36*WPU];
__device__ float         gM  [(size_t)36*WPV];
__device__ __nv_bfloat16 gqw_h[(size_t)2304*2304],    gqw_l[(size_t)2304*2304];
__device__ __nv_bfloat16 gkw_h[(size_t)2304*2304],    gkw_l[(size_t)2304*2304];
__device__ __nv_bfloat16 gvw_h[(size_t)2304*2304],    gvw_l[(size_t)2304*2304];
__device__ __nv_bfloat16 gw1t_h[(size_t)E2*Ee],       gw1t_l[(size_t)E2*Ee];
__device__ __nv_bfloat16 gw2f_h[(size_t)Ee*E2],       gw2f_l[(size_t)Ee*E2];
__device__ float         gdown[(size_t)Bsz*PLANE];
__device__ __nv_bfloat16 gdt_h[(size_t)Bsz*PLANE],  gdt_l[(size_t)Bsz*PLANE];
__device__ __nv_bfloat16 gq_h[(size_t)Bsz*PLANE],   gq_l[(size_t)Bsz*PLANE];
__device__ __nv_bfloat16 gk_h[(size_t)Bsz*PLANE],   gk_l[(size_t)Bsz*PLANE];
__device__ __nv_bfloat16 gv_h[(size_t)Bsz*PLANE],   gv_l[(size_t)Bsz*PLANE];
__device__ float         gqk[(size_t)Bsz*PLANE];
__device__ __nv_bfloat16 gat_h[(size_t)Bsz*PLANE],  gat_l[(size_t)Bsz*PLANE];
__device__ float         gh1p[(size_t)Bsz*PLANE],   gh1[(size_t)Bsz*PLANE];
__device__ __nv_bfloat16 gh1_h[(size_t)Bsz*PLANE],  gh1_l[(size_t)Bsz*PLANE];
__device__ __nv_bfloat16 gf_h[(size_t)9216*E2],     gf_l[(size_t)9216*E2];

// ---------------- PTX helpers ----------------
__device__ __forceinline__ uint32_t smem_u32(const void* p) {
    uint32_t a;
    asm("{ .reg .u64 t; cvta.to.shared.u64 t, %1; cvt.u32.u64 %0, t; }" : "=r"(a) : "l"(p));
    return a;
}
#define CP16(sa, gp)  asm volatile("cp.async.cg.shared.global [%0], [%1], 16;" :: "r"(sa), "l"(gp))
#define CP_COMMIT()   asm volatile("cp.async.commit_group;" ::: "memory")
#define CP_WAIT1()    asm volatile("cp.async.wait_group 1;" ::: "memory")
#define CP_WAIT0()    asm volatile("cp.async.wait_group 0;" ::: "memory")
#define LDSM4(r0, r1, r2, r3, a) \
    asm volatile("ldmatrix.sync.aligned.m8n8.x4.shared.b16 {%0,%1,%2,%3}, [%4];" \
        : "=r"(r0), "=r"(r1), "=r"(r2), "=r"(r3) : "r"(a))
#define LDSM2(r0, r1, a) \
    asm volatile("ldmatrix.sync.aligned.m8n8.x2.shared.b16 {%0,%1}, [%2];" \
        : "=r"(r0), "=r"(r1) : "r"(a))
#define MMA16816(d, a, bb2) \
    asm volatile("mma.sync.aligned.m16n8k16.row.col.f32.bf16.bf16.f32 " \
        "{%0,%1,%2,%3}, {%4,%5,%6,%7}, {%8,%9}, {%0,%1,%2,%3};" \
        : "+f"((d)[0]), "+f"((d)[1]), "+f"((d)[2]), "+f"((d)[3]) \
        : "r"((a)[0]), "r"((a)[1]), "r"((a)[2]), "r"((a)[3]), "r"((bb2)[0]), "r"((bb2)[1]))

__device__ __forceinline__ void st_split2(__nv_bfloat16* ph, __nv_bfloat16* pl, float v0, float v1) {
    __nv_bfloat162 hp, lp;
    hp.x = __float2bfloat16(v0); hp.y = __float2bfloat16(v1);
    lp.x = __float2bfloat16(v0 - __bfloat162float(hp.x));
    lp.y = __float2bfloat16(v1 - __bfloat162float(hp.y));
    *(__nv_bfloat162*)ph = hp;
    *(__nv_bfloat162*)pl = lp;
}
__device__ __forceinline__ void split1(float v, __nv_bfloat16* ph, __nv_bfloat16* pl) {
    __nv_bfloat16 h = __float2bfloat16(v);
    *ph = h; *pl = __float2bfloat16(v - __bfloat162float(h));
}

// ---------------- HMMA GEMM: 64x64 tile, BK=64, 2-stage, 128 threads, 3 CTAs/SM ----------------
// 4 warps (2m x 2n), each 32x32. EPI: 0 q/k | 1 v | 3 qk | 4 ao | 5 ffn1 | 6 ffn2 | 7 raw
constexpr int STG = 32768;            // Ah 8K | Al 8K | Bh 8K | Bl 8K
constexpr int SMEMSZ = 2 * STG;       // 64 KB -> 3 CTAs/SM

template<int EPI>
__global__ void __launch_bounds__(128, 3) gemm_hm(
    const __nv_bfloat16* __restrict__ Ah, const __nv_bfloat16* __restrict__ Al,
    const __nv_bfloat16* __restrict__ Bh, const __nv_bfloat16* __restrict__ Bl,
    int K, int lda, int ldb, size_t sA, size_t sB,
    __nv_bfloat16* __restrict__ o0, __nv_bfloat16* __restrict__ o1, float* __restrict__ pF,
    int ldc, size_t sC,
    const float* __restrict__ bias, const float* __restrict__ r0)
{
    extern __shared__ __align__(128) char smraw[];
    const int tid = threadIdx.x, b = blockIdx.z;
    const int row0 = blockIdx.x * 64, col0 = blockIdx.y * 64;
    const uint32_t sbase = smem_u32(smraw);
    const int w = tid >> 5, lane = tid & 31;
    const int wm = w & 1, wn = w >> 1;          // warp tile: 32(m) x 32(n)

    Ah += (size_t)b * sA; Al += (size_t)b * sA;
    Bh += (size_t)b * sB; Bl += (size_t)b * sB;

    float acc[2][4][4];
    #pragma unroll
    for (int i = 0; i < 2; i++)
        #pragma unroll
        for (int j = 0; j < 4; j++)
            #pragma unroll
            for (int c = 0; c < 4; c++) acc[i][j][c] = 0.f;

    const int nC = K >> 6;

    auto load_stage = [&](int ci) {
        const uint32_t stg = (uint32_t)(ci & 1) * (uint32_t)STG;
        const int kbase = ci << 6;
        #pragma unroll
        for (int i = 0; i < 4; i++) {           // 64 rows x 8 groups = 512 slots / 128 thr
            int e = i * 128 + tid;
            int r = e >> 3, g = e & 7;
            uint32_t so = (uint32_t)(r * 128 + ((g ^ (r & 7)) << 4));
            size_t aoff = (size_t)(row0 + r) * lda + kbase + g * 8;
            CP16(sbase + stg + so,          Ah + aoff);
            CP16(sbase + stg + 8192 + so,   Al + aoff);
            size_t boff = (size_t)(col0 + r) * ldb + kbase + g * 8;
            CP16(sbase + stg + 16384 + so,  Bh + boff);
            CP16(sbase + stg + 24576 + so,  Bl + boff);
        }
    };

    auto compute_stage = [&](int ci) {
        const uint32_t sb = sbase + (uint32_t)(ci & 1) * (uint32_t)STG;
        #pragma unroll
        for (int ks = 0; ks < 4; ks++) {
            uint32_t ah[2][4], al[2][4], bh[4][2], bl[4][2];
            const int ar = lane & 15, ac = lane >> 4;
            #pragma unroll
            for (int mi = 0; mi < 2; mi++) {
                int r = wm * 32 + mi * 16 + ar;
                int g = ks * 2 + ac;
                uint32_t off = (uint32_t)(r * 128 + ((g ^ (r & 7)) << 4));
                LDSM4(ah[mi][0], ah[mi][1], ah[mi][2], ah[mi][3], sb + off);
                LDSM4(al[mi][0], al[mi][1], al[mi][2], al[mi][3], sb + 8192 + off);
            }
            const int br = lane & 7, bc = (lane >> 3) & 1;
            #pragma unroll
            for (int ni = 0; ni < 4; ni++) {
                int r = wn * 32 + ni * 8 + br;
                int g = ks * 2 + bc;
                uint32_t off = (uint32_t)(r * 128 + ((g ^ (r & 7)) << 4));
                LDSM2(bh[ni][0], bh[ni][1], sb + 16384 + off);
                LDSM2(bl[ni][0], bl[ni][1], sb + 24576 + off);
            }
            #pragma unroll
            for (int mi = 0; mi < 2; mi++)
                #pragma unroll
                for (int ni = 0; ni < 4; ni++) {
                    MMA16816(acc[mi][ni], ah[mi], bh[ni]);
                    MMA16816(acc[mi][ni], ah[mi], bl[ni]);
                    MMA16816(acc[mi][ni], al[mi], bh[ni]);
                }
        }
    };

    load_stage(0); CP_COMMIT();
    #pragma unroll 1
    for (int ci = 0; ci < nC; ci++) {
        if (ci + 1 < nC) { load_stage(ci + 1); CP_COMMIT(); CP_WAIT1(); }
        else             { CP_WAIT0(); }
        __syncthreads();
        compute_stage(ci);
        __syncthreads();
    }

    // -------- epilogue --------
    const int lg = lane >> 2, lc = (lane & 3) * 2;
    #pragma unroll
    for (int mi = 0; mi < 2; mi++) {
        #pragma unroll
        for (int rr = 0; rr < 2; rr++) {
            const int gm = row0 + wm * 32 + mi * 16 + rr * 8 + lg;
            float rowb = 0.f;
            int ih = 0, iw = 0; size_t aorow = 0, resb = 0;
            if (EPI == 0) rowb = bias[gm];
            if (EPI == 3) { ih = gm / 48; iw = gm - ih * 48; }
            if (EPI == 4) {
                int bb = gm / 576, cc = (gm - bb * 576) * 4 + b;
                aorow = (size_t)bb * 2304 + cc;
                resb  = (size_t)bb * PLANE + cc;
            }
            #pragma unroll
            for (int ni = 0; ni < 4; ni++) {
                float v0 = acc[mi][ni][rr * 2 + 0];
                float v1 = acc[mi][ni][rr * 2 + 1];
                const int gn = col0 + wn * 32 + ni * 8 + lc;
                if (EPI == 0) { v0 += rowb; v1 += rowb; }
                else if (EPI == 1) { v0 += bias[gn]; v1 += bias[gn + 1]; }
                else if (EPI == 3) {
                    int jh = gn / 48, jw = gn - jh * 48;
                    int rbase = (ih - jh + 47) * 95 + (iw - jw + 47);
                    v0 = v0 * 0.0208333333333333f + bias[(rbase << 2) + b];
                    v1 = v1 * 0.0208333333333333f + bias[((rbase - 1) << 2) + b];
                } else if (EPI == 4) {
                    v0 += r0[resb + (size_t)gn * 2304];
                    v1 += r0[resb + (size_t)(gn + 1) * 2304];
                } else if (EPI == 5) {
                    v0 = fmaxf(v0 + bias[gn], 0.f);
                    v1 = fmaxf(v1 + bias[gn + 1], 0.f);
                } else if (EPI == 6) {
                    v0 += bias[gn]     + r0[(size_t)gm * ldc + gn];
                    v1 += bias[gn + 1] + r0[(size_t)gm * ldc + gn + 1];
                }
                size_t co = (size_t)gm * ldc + gn + (size_t)b * sC;
                if (EPI == 0 || EPI == 1 || EPI == 5) {
                    st_split2(o0 + co, o1 + co, v0, v1);
                } else if (EPI == 3 || EPI == 6 || EPI == 7) {
                    float2 f; f.x = v0; f.y = v1;
                    *(float2*)(pF + co) = f;
                } else if (EPI == 4) {
                    float2 f; f.x = v0; f.y = v1;
                    *(float2*)(pF + aorow * 2304 + gn) = f;
                }
            }
        }
    }
}

// ---------------- F(4,3) input transform with FUSED conv1+ReLU ----------------
__global__ void v_trans_k(const float* __restrict__ x, const float* __restrict__ w1,
                          const float* __restrict__ b1)
{
    int idx = blockIdx.x * blockDim.x + threadIdx.x;
    if (idx >= WT * 2304) return;
    int cin = idx % 2304, t = idx / 2304;
    if (t >= 576) {
        #pragma unroll
        for (int xi = 0; xi < 36; xi++) {
            size_t d = (size_t)xi * WPV + (size_t)t * 2304 + cin;
            gV_h[d] = __float2bfloat16(0.f);
            gV_l[d] = __float2bfloat16(0.f);
        }
        return;
    }
    int b = t / 144, tile = t % 144;
    int ty = tile / 12, tx = tile % 12;
    const float* xb = x + (size_t)b * 2304;
    float xp[8][8];
    #pragma unroll
    for (int rr = 0; rr < 8; rr++) {
        int gr = 4 * ty - 2 + rr;
        #pragma unroll
        for (int cc = 0; cc < 8; cc++) {
            int gc = 4 * tx - 2 + cc;
            xp[rr][cc] = (gr >= 0 && gr < 48 && gc >= 0 && gc < 48) ? xb[gr * 48 + gc] : 0.f;
        }
    }
    float wc[9];
    #pragma unroll
    for (int i = 0; i < 9; i++) wc[i] = w1[(size_t)cin * 9 + i];
    float bc = b1[cin];

    float d[6][6];
    #pragma unroll
    for (int r = 0; r < 6; r++) {
        int py = 4 * ty + r;
        #pragma unroll
        for (int c = 0; c < 6; c++) {
            int px = 4 * tx + c;
            float v = 0.f;
            if (py >= 1 && py <= 48 && px >= 1 && px <= 48) {
                float s = bc;
                #pragma unroll
                for (int kh = 0; kh < 3; kh++)
                    #pragma unroll
                    for (int kw = 0; kw < 3; kw++)
                        s += wc[kh * 3 + kw] * xp[r + kh][c + kw];
                v = fmaxf(s, 0.f);
            }
            d[r][c] = v;
        }
    }
    float t1[6][6];
    #pragma unroll
    for (int j = 0; j < 6; j++) {
        t1[0][j] =  4.f*d[0][j] - 5.f*d[2][j] + d[4][j];
        t1[1][j] = -4.f*d[1][j] - 4.f*d[2][j] + d[3][j] + d[4][j];
        t1[2][j] =  4.f*d[1][j] - 4.f*d[2][j] - d[3][j] + d[4][j];
        t1[3][j] = -2.f*d[1][j] -     d[2][j] + 2.f*d[3][j] + d[4][j];
        t1[4][j] =  2.f*d[1][j] -     d[2][j] - 2.f*d[3][j] + d[4][j];
        t1[5][j] =  4.f*d[1][j] - 5.f*d[3][j] + d[5][j];
    }
    size_t obase = (size_t)t * 2304 + cin;
    #pragma unroll
    for (int i = 0; i < 6; i++) {
        float vv[6];
        vv[0] =  4.f*t1[i][0] - 5.f*t1[i][2] + t1[i][4];
        vv[1] = -4.f*t1[i][1] - 4.f*t1[i][2] + t1[i][3] + t1[i][4];
        vv[2] =  4.f*t1[i][1] - 4.f*t1[i][2] - t1[i][3] + t1[i][4];
        vv[3] = -2.f*t1[i][1] -     t1[i][2] + 2.f*t1[i][3] + t1[i][4];
        vv[4] =  2.f*t1[i][1] -     t1[i][2] - 2.f*t1[i][3] + t1[i][4];
        vv[5] =  4.f*t1[i][1] - 5.f*t1[i][3] + t1[i][5];
        #pragma unroll
        for (int j = 0; j < 6; j++) {
            size_t dd = (size_t)(i * 6 + j) * WPV + obase;
            split1(vv[j], &gV_h[dd], &gV_l[dd]);
        }
    }
}

// ---------------- F(4,3) weight transform ----------------
__global__ void u_trans_k(const float* __restrict__ w2)
{
    int idx = blockIdx.x * blockDim.x + threadIdx.x;
    if (idx >= 2304 * 2304) return;
    int cin = idx % 2304, cout = idx / 2304;
    const float* g = w2 + (size_t)idx * 9;
    float gw[6][3];
    #pragma unroll
    for (int c = 0; c < 3; c++) {
        float g0 = g[c], g1 = g[3 + c], g2 = g[6 + c];
        gw[0][c] = 0.25f * g0;
        gw[1][c] = (-g0 - g1 - g2) * (1.f / 6.f);
        gw[2][c] = (-g0 + g1 - g2) * (1.f / 6.f);
        gw[3][c] = g0 * (1.f / 24.f) + g1 * (1.f / 12.f) + g2 * (1.f / 6.f);
        gw[4][c] = g0 * (1.f / 24.f) - g1 * (1.f / 12.f) + g2 * (1.f / 6.f);
        gw[5][c] = g2;
    }
    size_t base = (size_t)cout * 2304 + cin;
    #pragma unroll
    for (int i = 0; i < 6; i++) {
        float a = gw[i][0], bb = gw[i][1], cc = gw[i][2];
        float uu[6];
        uu[0] = 0.25f * a;
        uu[1] = (-a - bb - cc) * (1.f / 6.f);
        uu[2] = (-a + bb - cc) * (1.f / 6.f);
        uu[3] = a * (1.f / 24.f) + bb * (1.f / 12.f) + cc * (1.f / 6.f);
        uu[4] = a * (1.f / 24.f) - bb * (1.f / 12.f) + cc * (1.f / 6.f);
        uu[5] = cc;
        #pragma unroll
        for (int j = 0; j < 6; j++) {
            size_t d = (size_t)(i * 6 + j) * WPU + base;
            split1(uu[j], &gU_h[d], &gU_l[d]);
        }
    }
}

// ---------------- F(4,3) inverse + bias + identity + relu -> down^T ----------------
__global__ void winv_k(const float* __restrict__ x, const float* __restrict__ c2b,
                       const float* __restrict__ idw, const float* __restrict__ idb)
{
    int idx = blockIdx.x * blockDim.x + threadIdx.x;
    if (idx >= 576 * 2304) return;
    int cout = idx % 2304, t = idx / 2304;
    int b = t / 144, tile = t % 144;
    size_t mbase = (size_t)t * 2304 + cout;
    float m[6][6];
    #pragma unroll
    for (int xi = 0; xi < 36; xi++)
        m[xi / 6][xi % 6] = gM[(size_t)xi * WPV + mbase];
    float s[4][6];
    #pragma unroll
    for (int j = 0; j < 6; j++) {
        s[0][j] = m[0][j] + m[1][j] + m[2][j] +     m[3][j] +     m[4][j];
        s[1][j] =           m[1][j] - m[2][j] + 2.f*m[3][j] - 2.f*m[4][j];
        s[2][j] =           m[1][j] + m[2][j] + 4.f*m[3][j] + 4.f*m[4][j];
        s[3][j] =           m[1][j] - m[2][j] + 8.f*m[3][j] - 8.f*m[4][j] + m[5][j];
    }
    float y[4][4];
    #pragma unroll
    for (int i = 0; i < 4; i++) {
        y[i][0] = s[i][0] + s[i][1] + s[i][2] +     s[i][3] +     s[i][4];
        y[i][1] =           s[i][1] - s[i][2] + 2.f*s[i][3] - 2.f*s[i][4];
        y[i][2] =           s[i][1] + s[i][2] + 4.f*s[i][3] + 4.f*s[i][4];
        y[i][3] =           s[i][1] - s[i][2] + 8.f*s[i][3] - 8.f*s[i][4] + s[i][5];
    }
    int ty = tile / 12, tx = tile % 12;
    float cb = c2b[cout], iw = idw[cout], ib = idb[cout];
    const float* xb = x + (size_t)b * 2304;
    #pragma unroll
    for (int dy = 0; dy < 4; dy++)
        #pragma unroll
        for (int dx = 0; dx < 4; dx++) {
            int p = (4 * ty + dy) * 48 + 4 * tx + dx;
            float v = fmaxf(y[dy][dx] + cb + iw * xb[p] + ib, 0.f);
            size_t o = (size_t)b * PLANE + (size_t)p * 2304 + cout;
            gdown[o] = v;
            split1(v, &gdt_h[o], &gdt_l[o]);
        }
}

// ---------------- other prep kernels ----------------
__global__ void splitk(const float* __restrict__ s, __nv_bfloat16* __restrict__ h,
                       __nv_bfloat16* __restrict__ l, int n)
{
    int i = blockIdx.x * blockDim.x + threadIdx.x;
    if (i >= n) return;
    split1(s[i], h + i, l + i);
}

__global__ void tsplit(const float* __restrict__ src, __nv_bfloat16* __restrict__ dh,
                       __nv_bfloat16* __restrict__ dl, int R, int Cl)
{
    __shared__ float t[32][33];
    int c0 = blockIdx.x * 32, r0 = blockIdx.y * 32;
    for (int i = threadIdx.y; i < 32; i += 8)
        t[i][threadIdx.x] = src[(size_t)(r0 + i) * Cl + c0 + threadIdx.x];
    __syncthreads();
    for (int i = threadIdx.y; i < 32; i += 8) {
        float v = t[threadIdx.x][i];
        size_t d = (size_t)(c0 + i) * R + r0 + threadIdx.x;
        split1(v, &dh[d], &dl[d]);
    }
}

__global__ void softmax_split_k()
{
    size_t row = blockIdx.x;
    float* p = gqk + row * 2304;
    int t = threadIdx.x;
    float v[9], mx = -1e30f;
    #pragma unroll
    for (int i = 0; i < 9; i++) { v[i] = p[t + i*256]; mx = fmaxf(mx, v[i]); }
    __shared__ float red[256];
    red[t] = mx; __syncthreads();
    for (int s = 128; s > 0; s >>= 1) { if (t < s) red[t] = fmaxf(red[t], red[t+s]); __syncthreads(); }
    mx = red[0]; __syncthreads();
    float sum = 0.f;
    #pragma unroll
    for (int i = 0; i < 9; i++) { v[i] = __expf(v[i] - mx); sum += v[i]; }
    red[t] = sum; __syncthreads();
    for (int s = 128; s > 0; s >>= 1) { if (t < s) red[t] += red[t+s]; __syncthreads(); }
    float inv = 1.0f / red[0];
    #pragma unroll
    for (int i = 0; i < 9; i++) {
        size_t d = row * 2304 + t + i*256;
        split1(v[i] * inv, &gat_h[d], &gat_l[d]);
    }
}

template<bool SPLIT>
__global__ void ln_k(const float* __restrict__ in, float* __restrict__ out,
                     __nv_bfloat16* __restrict__ oh, __nv_bfloat16* __restrict__ ol,
                     const float* __restrict__ gam, const float* __restrict__ bet)
{
    size_t row = blockIdx.x;
    const float* p = in + row * Ee;
    int t = threadIdx.x;
    float v[9], s = 0.f;
    #pragma unroll
    for (int i = 0; i < 9; i++) { v[i] = p[t + i*256]; s += v[i]; }
    __shared__ float red[256];
    red[t] = s; __syncthreads();
    for (int st = 128; st > 0; st >>= 1) { if (t < st) red[t] += red[t+st]; __syncthreads(); }
    float mu = red[0] * (1.f / 2304.f); __syncthreads();
    float s2 = 0.f;
    #pragma unroll
    for (int i = 0; i < 9; i++) { float d = v[i] - mu; s2 += d * d; }
    red[t] = s2; __syncthreads();
    for (int st = 128; st > 0; st >>= 1) { if (t < st) red[t] += red[t+st]; __syncthreads(); }
    float rs = rsqrtf(red[0] * (1.f / 2304.f) + 1e-5f);
    #pragma unroll
    for (int i = 0; i < 9; i++) {
        int n = t + i*256;
        float r = (v[i] - mu) * rs * gam[n] + bet[n];
        out[row * Ee + n] = r;
        if (SPLIT) split1(r, &oh[row * Ee + n], &ol[row * Ee + n]);
    }
}

__global__ void maxpool_k(const float* __restrict__ in, float* __restrict__ out)
{
    int idx = blockIdx.x * blockDim.x + threadIdx.x;
    if (idx >= Bsz * Cc * 576) return;
    int r = idx % 576, bc = idx / 576, i = r / 24, j = r % 24;
    const float* pp = in + (size_t)bc * 2304 + (2*i) * 48 + 2*j;
    out[idx] = fmaxf(fmaxf(pp[0], pp[1]), fmaxf(pp[48], pp[49]));
}

// ---------------- launch ----------------
#define GAB(v, sym) __nv_bfloat16* v; { void* _p; cudaGetSymbolAddress(&_p, sym); v = (__nv_bfloat16*)_p; }
#define GAF(v, sym) float* v;         { void* _p; cudaGetSymbolAddress(&_p, sym); v = (float*)_p; }

extern "C" void kernel_launch(void* const* d_in, const int* in_sizes, int n_in,
                              void* d_out, int out_size)
{
    (void)in_sizes; (void)n_in; (void)out_size;
    const float* x       = (const float*)d_in[0];
    const float* conv1_w = (const float*)d_in[1];
    const float* conv1_b = (const float*)d_in[2];
    const float* conv2_w = (const float*)d_in[3];
    const float* conv2_b = (const float*)d_in[4];
    const float* id_w    = (const float*)d_in[5];
    const float* id_b    = (const float*)d_in[6];
    const float* q_w     = (const float*)d_in[7];
    const float* q_b     = (const float*)d_in[8];
    const float* k_w     = (const float*)d_in[9];
    const float* k_b     = (const float*)d_in[10];
    const float* v_w     = (const float*)d_in[11];
    const float* v_b     = (const float*)d_in[12];
    const float* rel_tab = (const float*)d_in[13];
    const float* ln1_g   = (const float*)d_in[14];
    const float* ln1_b   = (const float*)d_in[15];
    const float* ln2_g   = (const float*)d_in[16];
    const float* ln2_b   = (const float*)d_in[17];
    const float* ffn_w1  = (const float*)d_in[18];
    const float* ffn_b1  = (const float*)d_in[19];
    const float* ffn_w2  = (const float*)d_in[20];
    const float* ffn_b2  = (const float*)d_in[21];
    float* out  = (float*)d_out;
    float* pout = out + (size_t)Bsz * Cc * Np;

    GAB(pVh, gV_h)    GAB(pVl, gV_l)
    GAB(pUh, gU_h)    GAB(pUl, gU_l)
    GAF(pM, gM)
    GAB(pqwh, gqw_h)  GAB(pqwl, gqw_l)
    GAB(pkwh, gkw_h)  GAB(pkwl, gkw_l)
    GAB(pvwh, gvw_h)  GAB(pvwl, gvw_l)
    GAB(pw1h, gw1t_h) GAB(pw1l, gw1t_l)
    GAB(pw2fh, gw2f_h) GAB(pw2fl, gw2f_l)
    GAF(pdw, gdown)   GAB(pdth, gdt_h)  GAB(pdtl, gdt_l)
    GAB(pqh, gq_h)    GAB(pql, gq_l)
    GAB(pkh, gk_h)    GAB(pkl, gk_l)
    GAB(pvh, gv_h)    GAB(pvl, gv_l)
    GAF(pqk, gqk)
    GAB(path, gat_h)  GAB(patl, gat_l)
    GAF(ph1p, gh1p)   GAF(ph1, gh1)
    GAB(ph1h, gh1_h)  GAB(ph1l, gh1_l)
    GAB(pfh, gf_h)    GAB(pfl, gf_l)

    cudaFuncSetAttribute(gemm_hm<0>, cudaFuncAttributeMaxDynamicSharedMemorySize, SMEMSZ);
    cudaFuncSetAttribute(gemm_hm<1>, cudaFuncAttributeMaxDynamicSharedMemorySize, SMEMSZ);
    cudaFuncSetAttribute(gemm_hm<3>, cudaFuncAttributeMaxDynamicSharedMemorySize, SMEMSZ);
    cudaFuncSetAttribute(gemm_hm<4>, cudaFuncAttributeMaxDynamicSharedMemorySize, SMEMSZ);
    cudaFuncSetAttribute(gemm_hm<5>, cudaFuncAttributeMaxDynamicSharedMemorySize, SMEMSZ);
    cudaFuncSetAttribute(gemm_hm<6>, cudaFuncAttributeMaxDynamicSharedMemorySize, SMEMSZ);
    cudaFuncSetAttribute(gemm_hm<7>, cudaFuncAttributeMaxDynamicSharedMemorySize, SMEMSZ);

    // launches 0-4 prep; 5 = conv2 GEMM (profiled by ncu -s 5 -c 1)
    v_trans_k<<<(WT*2304 + 255)/256, 256>>>(x, conv1_w, conv1_b);
    u_trans_k<<<(2304*2304 + 255)/256, 256>>>(conv2_w);
    splitk<<<(2304*2304 + 255)/256, 256>>>(q_w, pqwh, pqwl, 2304*2304);
    splitk<<<(2304*2304 + 255)/256, 256>>>(k_w, pkwh, pkwl, 2304*2304);
    splitk<<<(2304*2304 + 255)/256, 256>>>(v_w, pvwh, pvwl, 2304*2304);

    // F(4,3) batched GEMM over all 36 planes
    gemm_hm<7><<<dim3(10,36,36), 128, SMEMSZ>>>(pVh, pVl, pUh, pUl,
        2304, 2304, 2304, WPV, WPU, nullptr, nullptr, pM, 2304, WPV, nullptr, nullptr);

    winv_k<<<(576*2304 + 255)/256, 256>>>(x, conv2_b, id_w, id_b);
    tsplit<<<dim3(E2/32, Ee/32), dim3(32,8)>>>(ffn_w1, pw1h, pw1l, Ee, E2);
    tsplit<<<dim3(Ee/32, E2/32), dim3(32,8)>>>(ffn_w2, pw2fh, pw2fl, E2, Ee);

    // q, k: D[e][p] = qw . down^T
    gemm_hm<0><<<dim3(36,36,Bsz), 128, SMEMSZ>>>(pqwh, pqwl, pdth, pdtl,
        2304, 2304, 2304, 0, PLANE, pqh, pql, nullptr, 2304, PLANE, q_b, nullptr);
    gemm_hm<0><<<dim3(36,36,Bsz), 128, SMEMSZ>>>(pkwh, pkwl, pdth, pdtl,
        2304, 2304, 2304, 0, PLANE, pkh, pkl, nullptr, 2304, PLANE, k_b, nullptr);
    // v^T: D[p][e] = down^T . vw
    gemm_hm<1><<<dim3(36,36,Bsz), 128, SMEMSZ>>>(pdth, pdtl, pvwh, pvwl,
        2304, 2304, 2304, PLANE, 0, pvh, pvl, nullptr, 2304, PLANE, v_b, nullptr);
    // qk = q.k^T/48 + relpos
    gemm_hm<3><<<dim3(36,36,Bsz), 128, SMEMSZ>>>(pqh, pql, pkh, pkl,
        2304, 2304, 2304, PLANE, PLANE, nullptr, nullptr, pqk, 2304, PLANE, rel_tab, nullptr);
    softmax_split_k<<<Bsz*Ee, 256>>>();
    // ao scatter + residual
    gemm_hm<4><<<dim3(36,36,Bsz), 128, SMEMSZ>>>(path, patl, pvh, pvl,
        2304, 2304, 2304, PLANE, PLANE, nullptr, nullptr, ph1p, 2304, 0, nullptr, pdw);
    ln_k<true><<<Bsz*Cc, 256>>>(ph1p, ph1, ph1h, ph1l, ln1_g, ln1_b);
    // ffn1
    gemm_hm<5><<<dim3(144,72,1), 128, SMEMSZ>>>(ph1h, ph1l, pw1h, pw1l,
        2304, 2304, 2304, 0, 0, pfh, pfl, nullptr, E2, 0, ffn_b1, nullptr);
    // ffn2 + residual -> d_out (pre-LN2)
    gemm_hm<6><<<dim3(144,36,1), 128, SMEMSZ>>>(pfh, pfl, pw2fh, pw2fl,
        E2, E2, E2, 0, 0, nullptr, nullptr, out, 2304, 0, ffn_b2, ph1);
    ln_k<false><<<Bsz*Cc, 256>>>(out, out, nullptr, nullptr, ln2_g, ln2_b);
    maxpool_k<<<(Bsz*Cc*576 + 255)/256, 256>>>(out, pout);
}

// round 17
// speedup vs baseline: 1.5342x; 1.5342x over previous
#include <cuda_runtime.h>
#include <cuda_bf16.h>
#include <cstdint>

constexpr int Bsz = 4, Np = 2304, Cc = 2304, Ee = 2304, E2 = 4608;
constexpr size_t PLANE = (size_t)Np * Cc;
constexpr int WT = 640;
constexpr size_t WPV = (size_t)WT * 2304;
constexpr size_t WPU = (size_t)2304 * 2304;

// ---------------- scratch ----------------
__device__ __nv_bfloat16 gV_h[(size_t)36*WPV], gV_l[(size_t)36*WPV];
__device__ __nv_bfloat16 gU_h[(size_t)36*WPU], gU_l[(size_t)36*WPU];
__device__ float         gM  [(size_t)36*WPV];
__device__ __nv_bfloat16 gqkw_h[(size_t)2*WPU], gqkw_l[(size_t)2*WPU];   // q | k weights
__device__ __nv_bfloat16 gvw_h[(size_t)2304*2304],    gvw_l[(size_t)2304*2304];
__device__ __nv_bfloat16 gw1t_h[(size_t)E2*Ee],       gw1t_l[(size_t)E2*Ee];
__device__ __nv_bfloat16 gw2f_h[(size_t)Ee*E2],       gw2f_l[(size_t)Ee*E2];
__device__ float         gdown[(size_t)Bsz*PLANE];
__device__ __nv_bfloat16 gdt_h[(size_t)Bsz*PLANE],  gdt_l[(size_t)Bsz*PLANE];
__device__ __nv_bfloat16 gqko_h[(size_t)8*PLANE],   gqko_l[(size_t)8*PLANE];  // q | k outputs
__device__ __nv_bfloat16 gv_h[(size_t)Bsz*PLANE],   gv_l[(size_t)Bsz*PLANE];
__device__ float         gqk[(size_t)Bsz*PLANE];
__device__ __nv_bfloat16 gat_h[(size_t)Bsz*PLANE],  gat_l[(size_t)Bsz*PLANE];
__device__ float         gh1p[(size_t)Bsz*PLANE],   gh1[(size_t)Bsz*PLANE];
__device__ __nv_bfloat16 gh1_h[(size_t)Bsz*PLANE],  gh1_l[(size_t)Bsz*PLANE];
__device__ __nv_bfloat16 gf_h[(size_t)9216*E2],     gf_l[(size_t)9216*E2];

// ---------------- PTX helpers ----------------
__device__ __forceinline__ uint32_t smem_u32(const void* p) {
    uint32_t a;
    asm("{ .reg .u64 t; cvta.to.shared.u64 t, %1; cvt.u32.u64 %0, t; }" : "=r"(a) : "l"(p));
    return a;
}
#define CP16(sa, gp)  asm volatile("cp.async.cg.shared.global [%0], [%1], 16;" :: "r"(sa), "l"(gp))
#define CP_COMMIT()   asm volatile("cp.async.commit_group;" ::: "memory")
#define CP_WAIT1()    asm volatile("cp.async.wait_group 1;" ::: "memory")
#define CP_WAIT0()    asm volatile("cp.async.wait_group 0;" ::: "memory")
#define LDSM4(r0, r1, r2, r3, a) \
    asm volatile("ldmatrix.sync.aligned.m8n8.x4.shared.b16 {%0,%1,%2,%3}, [%4];" \
        : "=r"(r0), "=r"(r1), "=r"(r2), "=r"(r3) : "r"(a))
#define LDSM2(r0, r1, a) \
    asm volatile("ldmatrix.sync.aligned.m8n8.x2.shared.b16 {%0,%1}, [%2];" \
        : "=r"(r0), "=r"(r1) : "r"(a))
#define MMA16816(d, a, bb2) \
    asm volatile("mma.sync.aligned.m16n8k16.row.col.f32.bf16.bf16.f32 " \
        "{%0,%1,%2,%3}, {%4,%5,%6,%7}, {%8,%9}, {%0,%1,%2,%3};" \
        : "+f"((d)[0]), "+f"((d)[1]), "+f"((d)[2]), "+f"((d)[3]) \
        : "r"((a)[0]), "r"((a)[1]), "r"((a)[2]), "r"((a)[3]), "r"((bb2)[0]), "r"((bb2)[1]))

__device__ __forceinline__ void st_split2(__nv_bfloat16* ph, __nv_bfloat16* pl, float v0, float v1) {
    __nv_bfloat162 hp, lp;
    hp.x = __float2bfloat16(v0); hp.y = __float2bfloat16(v1);
    lp.x = __float2bfloat16(v0 - __bfloat162float(hp.x));
    lp.y = __float2bfloat16(v1 - __bfloat162float(hp.y));
    *(__nv_bfloat162*)ph = hp;
    *(__nv_bfloat162*)pl = lp;
}
__device__ __forceinline__ void split1(float v, __nv_bfloat16* ph, __nv_bfloat16* pl) {
    __nv_bfloat16 h = __float2bfloat16(v);
    *ph = h; *pl = __float2bfloat16(v - __bfloat162float(h));
}

// ---------------- HMMA GEMM: 128x96 tile, BK=64, 2-stage, 256 threads, 2 CTAs/SM ----------------
// 8 warps (2m x 4n), each 64x24. EPI: 0 (+bias[m], split) | 1 v (+bias[n], split)
//   3 qk (scale+relpos, f32) | 4 ao (scatter+residual, f32) | 5 ffn1 (relu+bias[n], split)
//   6 ffn2 (f32+bias+res) | 7 raw f32 | 8 merged q/k (z = sel*4+b)
constexpr int STG = 57344;            // Ah 16K | Al 16K | Bh 12K | Bl 12K
constexpr int SMEMSZ = 2 * STG;       // 112 KB  -> 2 CTAs/SM

template<int EPI>
__global__ void __launch_bounds__(256, 2) gemm_hm(
    const __nv_bfloat16* __restrict__ Ah, const __nv_bfloat16* __restrict__ Al,
    const __nv_bfloat16* __restrict__ Bh, const __nv_bfloat16* __restrict__ Bl,
    int K, int lda, int ldb, size_t sA, size_t sB,
    __nv_bfloat16* __restrict__ o0, __nv_bfloat16* __restrict__ o1, float* __restrict__ pF,
    int ldc, size_t sC,
    const float* __restrict__ bias, const float* __restrict__ r0)
{
    extern __shared__ __align__(128) char smraw[];
    const int tid = threadIdx.x;
    int b, sel;
    if (EPI == 8) { b = blockIdx.z & 3; sel = blockIdx.z >> 2; }
    else          { b = blockIdx.z;     sel = 0; }
    const int row0 = blockIdx.x * 128, col0 = blockIdx.y * 96;
    const uint32_t sbase = smem_u32(smraw);
    const int w = tid >> 5, lane = tid & 31;
    const int wm = w & 1, wn = w >> 1;          // warp tile: 64(m) x 24(n)

    Ah += (size_t)b * sA + (size_t)sel * WPU;
    Al += (size_t)b * sA + (size_t)sel * WPU;
    Bh += (size_t)b * sB; Bl += (size_t)b * sB;

    float acc[4][3][4];
    #pragma unroll
    for (int i = 0; i < 4; i++)
        #pragma unroll
        for (int j = 0; j < 3; j++)
            #pragma unroll
            for (int c = 0; c < 4; c++) acc[i][j][c] = 0.f;

    const int nC = K >> 6;

    auto load_stage = [&](int ci) {
        const uint32_t stg = (uint32_t)(ci & 1) * (uint32_t)STG;
        const int kbase = ci << 6;
        #pragma unroll
        for (int i = 0; i < 4; i++) {
            int e = i * 256 + tid;
            int r = e >> 3, g = e & 7;
            uint32_t so = (uint32_t)(r * 128 + ((g ^ (r & 7)) << 4));
            size_t aoff = (size_t)(row0 + r) * lda + kbase + g * 8;
            CP16(sbase + stg + so,          Ah + aoff);
            CP16(sbase + stg + 16384 + so,  Al + aoff);
        }
        #pragma unroll
        for (int i = 0; i < 3; i++) {
            int e = i * 256 + tid;
            int r = e >> 3, g = e & 7;
            uint32_t so = (uint32_t)(r * 128 + ((g ^ (r & 7)) << 4));
            size_t boff = (size_t)(col0 + r) * ldb + kbase + g * 8;
            CP16(sbase + stg + 32768 + so,  Bh + boff);
            CP16(sbase + stg + 45056 + so,  Bl + boff);
        }
    };

    auto compute_stage = [&](int ci) {
        const uint32_t sb = sbase + (uint32_t)(ci & 1) * (uint32_t)STG;
        #pragma unroll
        for (int ks = 0; ks < 4; ks++) {
            uint32_t ah[4][4], al[4][4], bh[3][2], bl[3][2];
            const int ar = lane & 15, ac = lane >> 4;
            #pragma unroll
            for (int mi = 0; mi < 4; mi++) {
                int r = wm * 64 + mi * 16 + ar;
                int g = ks * 2 + ac;
                uint32_t off = (uint32_t)(r * 128 + ((g ^ (r & 7)) << 4));
                LDSM4(ah[mi][0], ah[mi][1], ah[mi][2], ah[mi][3], sb + off);
                LDSM4(al[mi][0], al[mi][1], al[mi][2], al[mi][3], sb + 16384 + off);
            }
            const int br = lane & 7, bc = (lane >> 3) & 1;
            #pragma unroll
            for (int ni = 0; ni < 3; ni++) {
                int r = wn * 24 + ni * 8 + br;
                int g = ks * 2 + bc;
                uint32_t off = (uint32_t)(r * 128 + ((g ^ (r & 7)) << 4));
                LDSM2(bh[ni][0], bh[ni][1], sb + 32768 + off);
                LDSM2(bl[ni][0], bl[ni][1], sb + 45056 + off);
            }
            #pragma unroll
            for (int mi = 0; mi < 4; mi++)
                #pragma unroll
                for (int ni = 0; ni < 3; ni++) {
                    MMA16816(acc[mi][ni], ah[mi], bh[ni]);
                    MMA16816(acc[mi][ni], ah[mi], bl[ni]);
                    MMA16816(acc[mi][ni], al[mi], bh[ni]);
                }
        }
    };

    load_stage(0); CP_COMMIT();
    #pragma unroll 1
    for (int ci = 0; ci < nC; ci++) {
        if (ci + 1 < nC) { load_stage(ci + 1); CP_COMMIT(); CP_WAIT1(); }
        else             { CP_WAIT0(); }
        __syncthreads();
        compute_stage(ci);
        __syncthreads();
    }

    // -------- epilogue --------
    const int lg = lane >> 2, lc = (lane & 3) * 2;
    #pragma unroll
    for (int mi = 0; mi < 4; mi++) {
        #pragma unroll
        for (int rr = 0; rr < 2; rr++) {
            const int gm = row0 + wm * 64 + mi * 16 + rr * 8 + lg;
            float rowb = 0.f;
            int ih = 0, iw = 0; size_t aorow = 0, resb = 0;
            if (EPI == 0) rowb = bias[gm];
            if (EPI == 8) rowb = (sel ? r0 : bias)[gm];
            if (EPI == 3) { ih = gm / 48; iw = gm - ih * 48; }
            if (EPI == 4) {
                int bb = gm / 576, cc = (gm - bb * 576) * 4 + b;
                aorow = (size_t)bb * 2304 + cc;
                resb  = (size_t)bb * PLANE + cc;
            }
            #pragma unroll
            for (int ni = 0; ni < 3; ni++) {
                float v0 = acc[mi][ni][rr * 2 + 0];
                float v1 = acc[mi][ni][rr * 2 + 1];
                const int gn = col0 + wn * 24 + ni * 8 + lc;
                if (EPI == 0 || EPI == 8) { v0 += rowb; v1 += rowb; }
                else if (EPI == 1) { v0 += bias[gn]; v1 += bias[gn + 1]; }
                else if (EPI == 3) {
                    int jh = gn / 48, jw = gn - jh * 48;
                    int rbase = (ih - jh + 47) * 95 + (iw - jw + 47);
                    v0 = v0 * 0.0208333333333333f + bias[(rbase << 2) + b];
                    v1 = v1 * 0.0208333333333333f + bias[((rbase - 1) << 2) + b];
                } else if (EPI == 4) {
                    v0 += r0[resb + (size_t)gn * 2304];
                    v1 += r0[resb + (size_t)(gn + 1) * 2304];
                } else if (EPI == 5) {
                    v0 = fmaxf(v0 + bias[gn], 0.f);
                    v1 = fmaxf(v1 + bias[gn + 1], 0.f);
                } else if (EPI == 6) {
                    v0 += bias[gn]     + r0[(size_t)gm * ldc + gn];
                    v1 += bias[gn + 1] + r0[(size_t)gm * ldc + gn + 1];
                }
                size_t co = (size_t)gm * ldc + gn + (size_t)b * sC + (size_t)sel * 4 * PLANE;
                if (EPI == 0 || EPI == 1 || EPI == 5 || EPI == 8) {
                    st_split2(o0 + co, o1 + co, v0, v1);
                } else if (EPI == 3 || EPI == 6 || EPI == 7) {
                    float2 f; f.x = v0; f.y = v1;
                    *(float2*)(pF + co) = f;
                } else if (EPI == 4) {
                    float2 f; f.x = v0; f.y = v1;
                    *(float2*)(pF + aorow * 2304 + gn) = f;
                }
            }
        }
    }
}

// ---------------- F(4,3) input transform with FUSED conv1+ReLU ----------------
__global__ void v_trans_k(const float* __restrict__ x, const float* __restrict__ w1,
                          const float* __restrict__ b1)
{
    int idx = blockIdx.x * blockDim.x + threadIdx.x;
    if (idx >= WT * 2304) return;
    int cin = idx % 2304, t = idx / 2304;
    if (t >= 576) {
        #pragma unroll
        for (int xi = 0; xi < 36; xi++) {
            size_t d = (size_t)xi * WPV + (size_t)t * 2304 + cin;
            gV_h[d] = __float2bfloat16(0.f);
            gV_l[d] = __float2bfloat16(0.f);
        }
        return;
    }
    int b = t / 144, tile = t % 144;
    int ty = tile / 12, tx = tile % 12;
    const float* xb = x + (size_t)b * 2304;
    float xp[8][8];
    #pragma unroll
    for (int rr = 0; rr < 8; rr++) {
        int gr = 4 * ty - 2 + rr;
        #pragma unroll
        for (int cc = 0; cc < 8; cc++) {
            int gc = 4 * tx - 2 + cc;
            xp[rr][cc] = (gr >= 0 && gr < 48 && gc >= 0 && gc < 48) ? xb[gr * 48 + gc] : 0.f;
        }
    }
    float wc[9];
    #pragma unroll
    for (int i = 0; i < 9; i++) wc[i] = w1[(size_t)cin * 9 + i];
    float bc = b1[cin];

    float d[6][6];
    #pragma unroll
    for (int r = 0; r < 6; r++) {
        int py = 4 * ty + r;
        #pragma unroll
        for (int c = 0; c < 6; c++) {
            int px = 4 * tx + c;
            float v = 0.f;
            if (py >= 1 && py <= 48 && px >= 1 && px <= 48) {
                float s = bc;
                #pragma unroll
                for (int kh = 0; kh < 3; kh++)
                    #pragma unroll
                    for (int kw = 0; kw < 3; kw++)
                        s += wc[kh * 3 + kw] * xp[r + kh][c + kw];
                v = fmaxf(s, 0.f);
            }
            d[r][c] = v;
        }
    }
    float t1[6][6];
    #pragma unroll
    for (int j = 0; j < 6; j++) {
        t1[0][j] =  4.f*d[0][j] - 5.f*d[2][j] + d[4][j];
        t1[1][j] = -4.f*d[1][j] - 4.f*d[2][j] + d[3][j] + d[4][j];
        t1[2][j] =  4.f*d[1][j] - 4.f*d[2][j] - d[3][j] + d[4][j];
        t1[3][j] = -2.f*d[1][j] -     d[2][j] + 2.f*d[3][j] + d[4][j];
        t1[4][j] =  2.f*d[1][j] -     d[2][j] - 2.f*d[3][j] + d[4][j];
        t1[5][j] =  4.f*d[1][j] - 5.f*d[3][j] + d[5][j];
    }
    size_t obase = (size_t)t * 2304 + cin;
    #pragma unroll
    for (int i = 0; i < 6; i++) {
        float vv[6];
        vv[0] =  4.f*t1[i][0] - 5.f*t1[i][2] + t1[i][4];
        vv[1] = -4.f*t1[i][1] - 4.f*t1[i][2] + t1[i][3] + t1[i][4];
        vv[2] =  4.f*t1[i][1] - 4.f*t1[i][2] - t1[i][3] + t1[i][4];
        vv[3] = -2.f*t1[i][1] -     t1[i][2] + 2.f*t1[i][3] + t1[i][4];
        vv[4] =  2.f*t1[i][1] -     t1[i][2] - 2.f*t1[i][3] + t1[i][4];
        vv[5] =  4.f*t1[i][1] - 5.f*t1[i][3] + t1[i][5];
        #pragma unroll
        for (int j = 0; j < 6; j++) {
            size_t dd = (size_t)(i * 6 + j) * WPV + obase;
            split1(vv[j], &gV_h[dd], &gV_l[dd]);
        }
    }
}

// ---------------- F(4,3) weight transform ----------------
__global__ void u_trans_k(const float* __restrict__ w2)
{
    int idx = blockIdx.x * blockDim.x + threadIdx.x;
    if (idx >= 2304 * 2304) return;
    int cin = idx % 2304, cout = idx / 2304;
    const float* g = w2 + (size_t)idx * 9;
    float gw[6][3];
    #pragma unroll
    for (int c = 0; c < 3; c++) {
        float g0 = g[c], g1 = g[3 + c], g2 = g[6 + c];
        gw[0][c] = 0.25f * g0;
        gw[1][c] = (-g0 - g1 - g2) * (1.f / 6.f);
        gw[2][c] = (-g0 + g1 - g2) * (1.f / 6.f);
        gw[3][c] = g0 * (1.f / 24.f) + g1 * (1.f / 12.f) + g2 * (1.f / 6.f);
        gw[4][c] = g0 * (1.f / 24.f) - g1 * (1.f / 12.f) + g2 * (1.f / 6.f);
        gw[5][c] = g2;
    }
    size_t base = (size_t)cout * 2304 + cin;
    #pragma unroll
    for (int i = 0; i < 6; i++) {
        float a = gw[i][0], bb = gw[i][1], cc = gw[i][2];
        float uu[6];
        uu[0] = 0.25f * a;
        uu[1] = (-a - bb - cc) * (1.f / 6.f);
        uu[2] = (-a + bb - cc) * (1.f / 6.f);
        uu[3] = a * (1.f / 24.f) + bb * (1.f / 12.f) + cc * (1.f / 6.f);
        uu[4] = a * (1.f / 24.f) - bb * (1.f / 12.f) + cc * (1.f / 6.f);
        uu[5] = cc;
        #pragma unroll
        for (int j = 0; j < 6; j++) {
            size_t d = (size_t)(i * 6 + j) * WPU + base;
            split1(uu[j], &gU_h[d], &gU_l[d]);
        }
    }
}

// ---------------- F(4,3) inverse + bias + identity + relu -> down^T ----------------
__global__ void winv_k(const float* __restrict__ x, const float* __restrict__ c2b,
                       const float* __restrict__ idw, const float* __restrict__ idb)
{
    int idx = blockIdx.x * blockDim.x + threadIdx.x;
    if (idx >= 576 * 2304) return;
    int cout = idx % 2304, t = idx / 2304;
    int b = t / 144, tile = t % 144;
    size_t mbase = (size_t)t * 2304 + cout;
    float m[6][6];
    #pragma unroll
    for (int xi = 0; xi < 36; xi++)
        m[xi / 6][xi % 6] = gM[(size_t)xi * WPV + mbase];
    float s[4][6];
    #pragma unroll
    for (int j = 0; j < 6; j++) {
        s[0][j] = m[0][j] + m[1][j] + m[2][j] +     m[3][j] +     m[4][j];
        s[1][j] =           m[1][j] - m[2][j] + 2.f*m[3][j] - 2.f*m[4][j];
        s[2][j] =           m[1][j] + m[2][j] + 4.f*m[3][j] + 4.f*m[4][j];
        s[3][j] =           m[1][j] - m[2][j] + 8.f*m[3][j] - 8.f*m[4][j] + m[5][j];
    }
    float y[4][4];
    #pragma unroll
    for (int i = 0; i < 4; i++) {
        y[i][0] = s[i][0] + s[i][1] + s[i][2] +     s[i][3] +     s[i][4];
        y[i][1] =           s[i][1] - s[i][2] + 2.f*s[i][3] - 2.f*s[i][4];
        y[i][2] =           s[i][1] + s[i][2] + 4.f*s[i][3] + 4.f*s[i][4];
        y[i][3] =           s[i][1] - s[i][2] + 8.f*s[i][3] - 8.f*s[i][4] + s[i][5];
    }
    int ty = tile / 12, tx = tile % 12;
    float cb = c2b[cout], iw = idw[cout], ib = idb[cout];
    const float* xb = x + (size_t)b * 2304;
    #pragma unroll
    for (int dy = 0; dy < 4; dy++)
        #pragma unroll
        for (int dx = 0; dx < 4; dx++) {
            int p = (4 * ty + dy) * 48 + 4 * tx + dx;
            float v = fmaxf(y[dy][dx] + cb + iw * xb[p] + ib, 0.f);
            size_t o = (size_t)b * PLANE + (size_t)p * 2304 + cout;
            gdown[o] = v;
            split1(v, &gdt_h[o], &gdt_l[o]);
        }
}

// ---------------- other prep kernels ----------------
__global__ void splitk(const float* __restrict__ s, __nv_bfloat16* __restrict__ h,
                       __nv_bfloat16* __restrict__ l, int n)
{
    int i = blockIdx.x * blockDim.x + threadIdx.x;
    if (i >= n) return;
    split1(s[i], h + i, l + i);
}

__global__ void tsplit(const float* __restrict__ src, __nv_bfloat16* __restrict__ dh,
                       __nv_bfloat16* __restrict__ dl, int R, int Cl)
{
    __shared__ float t[32][33];
    int c0 = blockIdx.x * 32, r0 = blockIdx.y * 32;
    for (int i = threadIdx.y; i < 32; i += 8)
        t[i][threadIdx.x] = src[(size_t)(r0 + i) * Cl + c0 + threadIdx.x];
    __syncthreads();
    for (int i = threadIdx.y; i < 32; i += 8) {
        float v = t[threadIdx.x][i];
        size_t d = (size_t)(c0 + i) * R + r0 + threadIdx.x;
        split1(v, &dh[d], &dl[d]);
    }
}

__global__ void softmax_split_k()
{
    size_t row = blockIdx.x;
    float* p = gqk + row * 2304;
    int t = threadIdx.x;
    float v[9], mx = -1e30f;
    #pragma unroll
    for (int i = 0; i < 9; i++) { v[i] = p[t + i*256]; mx = fmaxf(mx, v[i]); }
    __shared__ float red[256];
    red[t] = mx; __syncthreads();
    for (int s = 128; s > 0; s >>= 1) { if (t < s) red[t] = fmaxf(red[t], red[t+s]); __syncthreads(); }
    mx = red[0]; __syncthreads();
    float sum = 0.f;
    #pragma unroll
    for (int i = 0; i < 9; i++) { v[i] = __expf(v[i] - mx); sum += v[i]; }
    red[t] = sum; __syncthreads();
    for (int s = 128; s > 0; s >>= 1) { if (t < s) red[t] += red[t+s]; __syncthreads(); }
    float inv = 1.0f / red[0];
    #pragma unroll
    for (int i = 0; i < 9; i++) {
        size_t d = row * 2304 + t + i*256;
        split1(v[i] * inv, &gat_h[d], &gat_l[d]);
    }
}

template<bool SPLIT>
__global__ void ln_k(const float* __restrict__ in, float* __restrict__ out,
                     __nv_bfloat16* __restrict__ oh, __nv_bfloat16* __restrict__ ol,
                     const float* __restrict__ gam, const float* __restrict__ bet)
{
    size_t row = blockIdx.x;
    const float* p = in + row * Ee;
    int t = threadIdx.x;
    float v[9], s = 0.f;
    #pragma unroll
    for (int i = 0; i < 9; i++) { v[i] = p[t + i*256]; s += v[i]; }
    __shared__ float red[256];
    red[t] = s; __syncthreads();
    for (int st = 128; st > 0; st >>= 1) { if (t < st) red[t] += red[t+st]; __syncthreads(); }
    float mu = red[0] * (1.f / 2304.f); __syncthreads();
    float s2 = 0.f;
    #pragma unroll
    for (int i = 0; i < 9; i++) { float d = v[i] - mu; s2 += d * d; }
    red[t] = s2; __syncthreads();
    for (int st = 128; st > 0; st >>= 1) { if (t < st) red[t] += red[t+st]; __syncthreads(); }
    float rs = rsqrtf(red[0] * (1.f / 2304.f) + 1e-5f);
    #pragma unroll
    for (int i = 0; i < 9; i++) {
        int n = t + i*256;
        float r = (v[i] - mu) * rs * gam[n] + bet[n];
        out[row * Ee + n] = r;
        if (SPLIT) split1(r, &oh[row * Ee + n], &ol[row * Ee + n]);
    }
}

__global__ void maxpool_k(const float* __restrict__ in, float* __restrict__ out)
{
    int idx = blockIdx.x * blockDim.x + threadIdx.x;
    if (idx >= Bsz * Cc * 576) return;
    int r = idx % 576, bc = idx / 576, i = r / 24, j = r % 24;
    const float* pp = in + (size_t)bc * 2304 + (2*i) * 48 + 2*j;
    out[idx] = fmaxf(fmaxf(pp[0], pp[1]), fmaxf(pp[48], pp[49]));
}

// ---------------- launch ----------------
#define GAB(v, sym) __nv_bfloat16* v; { void* _p; cudaGetSymbolAddress(&_p, sym); v = (__nv_bfloat16*)_p; }
#define GAF(v, sym) float* v;         { void* _p; cudaGetSymbolAddress(&_p, sym); v = (float*)_p; }

extern "C" void kernel_launch(void* const* d_in, const int* in_sizes, int n_in,
                              void* d_out, int out_size)
{
    (void)in_sizes; (void)n_in; (void)out_size;
    const float* x       = (const float*)d_in[0];
    const float* conv1_w = (const float*)d_in[1];
    const float* conv1_b = (const float*)d_in[2];
    const float* conv2_w = (const float*)d_in[3];
    const float* conv2_b = (const float*)d_in[4];
    const float* id_w    = (const float*)d_in[5];
    const float* id_b    = (const float*)d_in[6];
    const float* q_w     = (const float*)d_in[7];
    const float* q_b     = (const float*)d_in[8];
    const float* k_w     = (const float*)d_in[9];
    const float* k_b     = (const float*)d_in[10];
    const float* v_w     = (const float*)d_in[11];
    const float* v_b     = (const float*)d_in[12];
    const float* rel_tab = (const float*)d_in[13];
    const float* ln1_g   = (const float*)d_in[14];
    const float* ln1_b   = (const float*)d_in[15];
    const float* ln2_g   = (const float*)d_in[16];
    const float* ln2_b   = (const float*)d_in[17];
    const float* ffn_w1  = (const float*)d_in[18];
    const float* ffn_b1  = (const float*)d_in[19];
    const float* ffn_w2  = (const float*)d_in[20];
    const float* ffn_b2  = (const float*)d_in[21];
    float* out  = (float*)d_out;
    float* pout = out + (size_t)Bsz * Cc * Np;

    GAB(pVh, gV_h)    GAB(pVl, gV_l)
    GAB(pUh, gU_h)    GAB(pUl, gU_l)
    GAF(pM, gM)
    GAB(pqkwh, gqkw_h) GAB(pqkwl, gqkw_l)
    GAB(pvwh, gvw_h)  GAB(pvwl, gvw_l)
    GAB(pw1h, gw1t_h) GAB(pw1l, gw1t_l)
    GAB(pw2fh, gw2f_h) GAB(pw2fl, gw2f_l)
    GAF(pdw, gdown)   GAB(pdth, gdt_h)  GAB(pdtl, gdt_l)
    GAB(pqkoh, gqko_h) GAB(pqkol, gqko_l)
    GAB(pvh, gv_h)    GAB(pvl, gv_l)
    GAF(pqk, gqk)
    GAB(path, gat_h)  GAB(patl, gat_l)
    GAF(ph1p, gh1p)   GAF(ph1, gh1)
    GAB(ph1h, gh1_h)  GAB(ph1l, gh1_l)
    GAB(pfh, gf_h)    GAB(pfl, gf_l)

    cudaFuncSetAttribute(gemm_hm<1>, cudaFuncAttributeMaxDynamicSharedMemorySize, SMEMSZ);
    cudaFuncSetAttribute(gemm_hm<3>, cudaFuncAttributeMaxDynamicSharedMemorySize, SMEMSZ);
    cudaFuncSetAttribute(gemm_hm<4>, cudaFuncAttributeMaxDynamicSharedMemorySize, SMEMSZ);
    cudaFuncSetAttribute(gemm_hm<5>, cudaFuncAttributeMaxDynamicSharedMemorySize, SMEMSZ);
    cudaFuncSetAttribute(gemm_hm<6>, cudaFuncAttributeMaxDynamicSharedMemorySize, SMEMSZ);
    cudaFuncSetAttribute(gemm_hm<7>, cudaFuncAttributeMaxDynamicSharedMemorySize, SMEMSZ);
    cudaFuncSetAttribute(gemm_hm<8>, cudaFuncAttributeMaxDynamicSharedMemorySize, SMEMSZ);

    // launches 0-4 prep; 5 = conv2 GEMM (profiled by ncu -s 5 -c 1)
    v_trans_k<<<(WT*2304 + 255)/256, 256>>>(x, conv1_w, conv1_b);
    u_trans_k<<<(2304*2304 + 255)/256, 256>>>(conv2_w);
    splitk<<<(2304*2304 + 255)/256, 256>>>(q_w, pqkwh, pqkwl, 2304*2304);
    splitk<<<(2304*2304 + 255)/256, 256>>>(k_w, pqkwh + WPU, pqkwl + WPU, 2304*2304);
    splitk<<<(2304*2304 + 255)/256, 256>>>(v_w, pvwh, pvwl, 2304*2304);

    // F(4,3) batched GEMM over all 36 planes
    gemm_hm<7><<<dim3(5,24,36), 256, SMEMSZ>>>(pVh, pVl, pUh, pUl,
        2304, 2304, 2304, WPV, WPU, nullptr, nullptr, pM, 2304, WPV, nullptr, nullptr);

    winv_k<<<(576*2304 + 255)/256, 256>>>(x, conv2_b, id_w, id_b);
    tsplit<<<dim3(E2/32, Ee/32), dim3(32,8)>>>(ffn_w1, pw1h, pw1l, Ee, E2);
    tsplit<<<dim3(Ee/32, E2/32), dim3(32,8)>>>(ffn_w2, pw2fh, pw2fl, E2, Ee);

    // merged q,k: z = sel*4+b ; D[e][p] = {qw,kw} . down^T
    gemm_hm<8><<<dim3(18,24,8), 256, SMEMSZ>>>(pqkwh, pqkwl, pdth, pdtl,
        2304, 2304, 2304, 0, PLANE, pqkoh, pqkol, nullptr, 2304, PLANE, q_b, k_b);
    // v^T: D[p][e] = down^T . vw
    gemm_hm<1><<<dim3(18,24,Bsz), 256, SMEMSZ>>>(pdth, pdtl, pvwh, pvwl,
        2304, 2304, 2304, PLANE, 0, pvh, pvl, nullptr, 2304, PLANE, v_b, nullptr);
    // qk = q.k^T/48 + relpos   (A = q half, B = k half)
    gemm_hm<3><<<dim3(18,24,Bsz), 256, SMEMSZ>>>(pqkoh, pqkol, pqkoh + 4*PLANE, pqkol + 4*PLANE,
        2304, 2304, 2304, PLANE, PLANE, nullptr, nullptr, pqk, 2304, PLANE, rel_tab, nullptr);
    softmax_split_k<<<Bsz*Ee, 256>>>();
    // ao scatter + residual
    gemm_hm<4><<<dim3(18,24,Bsz), 256, SMEMSZ>>>(path, patl, pvh, pvl,
        2304, 2304, 2304, PLANE, PLANE, nullptr, nullptr, ph1p, 2304, 0, nullptr, pdw);
    ln_k<true><<<Bsz*Cc, 256>>>(ph1p, ph1, ph1h, ph1l, ln1_g, ln1_b);
    // ffn1
    gemm_hm<5><<<dim3(72,48,1), 256, SMEMSZ>>>(ph1h, ph1l, pw1h, pw1l,
        2304, 2304, 2304, 0, 0, pfh, pfl, nullptr, E2, 0, ffn_b1, nullptr);
    // ffn2 + residual -> d_out (pre-LN2)
    gemm_hm<6><<<dim3(72,24,1), 256, SMEMSZ>>>(pfh, pfl, pw2fh, pw2fl,
        E2, E2, E2, 0, 0, nullptr, nullptr, out, 2304, 0, ffn_b2, ph1);
    ln_k<false><<<Bsz*Cc, 256>>>(out, out, nullptr, nullptr, ln2_g, ln2_b);
    maxpool_k<<<(Bsz*Cc*576 + 255)/256, 256>>>(out, pout);
}